// round 3
// baseline (speedup 1.0000x reference)
#include <cuda_runtime.h>

#define NW   162
#define CCH  128          // channels
#define CV4  (CCH / 4)    // float4 per row
#define MAXN 65536

// Scratch (allocation-free rule: __device__ globals)
__device__ int g_counts[NW];
__device__ int g_offsets[NW];
__device__ int g_order[MAXN];

__global__ void k_clear() {
    int i = threadIdx.x;
    if (i < NW) g_counts[i] = 0;
}

__global__ void k_hist(const int* __restrict__ wid, int N) {
    __shared__ int sh[NW];
    for (int i = threadIdx.x; i < NW; i += blockDim.x) sh[i] = 0;
    __syncthreads();
    for (int i = blockIdx.x * blockDim.x + threadIdx.x; i < N;
         i += gridDim.x * blockDim.x)
        atomicAdd(&sh[wid[i]], 1);
    __syncthreads();
    for (int i = threadIdx.x; i < NW; i += blockDim.x) {
        int v = sh[i];
        if (v) atomicAdd(&g_counts[i], v);
    }
}

// Exclusive scan of 162 counts (serial in one thread: trivial size),
// plus optionally emit counts (as float) into the output tail.
__global__ void k_scan(float* __restrict__ counts_f, int write_tail) {
    if (threadIdx.x == 0) {
        int run = 0;
        for (int w = 0; w < NW; ++w) {
            g_offsets[w] = run;
            run += g_counts[w];
        }
    }
    __syncthreads();
    if (write_tail) {
        for (int w = threadIdx.x; w < NW; w += blockDim.x)
            counts_f[w] = (float)g_counts[w];
    }
}

// Stable argsort by counting-sort: one block per window value.
// wid[] (164 KB) is L2-resident, so the 162 passes are cheap.
__global__ void k_order(const int* __restrict__ wid, int N,
                        float* __restrict__ order_f, int write_tail) {
    const int w = blockIdx.x;
    __shared__ int wsum[8];
    const int lane = threadIdx.x & 31;
    const int wu   = threadIdx.x >> 5;

    int base = g_offsets[w];  // broadcast load, same for all threads

    for (int t0 = 0; t0 < N; t0 += (int)blockDim.x) {
        int i = t0 + threadIdx.x;
        bool f = (i < N) && (wid[i] == w);
        unsigned bal = __ballot_sync(0xffffffffu, f);
        if (lane == 0) wsum[wu] = __popc(bal);
        __syncthreads();
        int pre = 0, tot = 0;
#pragma unroll
        for (int j = 0; j < 8; ++j) {
            int s = wsum[j];
            tot += s;
            if (j < wu) pre += s;
        }
        if (f) {
            int pos = base + pre + __popc(bal & ((1u << lane) - 1u));
            g_order[pos] = i;
            if (write_tail) order_f[pos] = (float)i;
        }
        base += tot;
        __syncthreads();  // protect wsum before next tile's write
    }
}

// One warp per output row (b, w, p): 32 lanes x float4 = 128 floats.
// Padding rows (p >= counts[w]) are zero-filled (d_out is poisoned).
__global__ void k_gather(const float4* __restrict__ x,
                         float4* __restrict__ out,
                         int N, int maxw, int rows) {
    long long gwarp = ((long long)blockIdx.x * blockDim.x + threadIdx.x) >> 5;
    int lane = threadIdx.x & 31;
    if (gwarp >= rows) return;
    int r = (int)gwarp;

    int nwmax = NW * maxw;
    int b   = r / nwmax;
    int rem = r - b * nwmax;
    int w   = rem / maxw;
    int p   = rem - w * maxw;

    float4 v = make_float4(0.f, 0.f, 0.f, 0.f);
    if (p < g_counts[w]) {
        int idx = g_order[g_offsets[w] + p];
        v = __ldg(&x[((long long)b * N + idx) * CV4 + lane]);
    }
    out[(long long)r * CV4 + lane] = v;
}

extern "C" void kernel_launch(void* const* d_in, const int* in_sizes, int n_in,
                              void* d_out, int out_size) {
    const float* x   = (const float*)d_in[0];
    const int*   wid = (const int*)d_in[1];

    const int N = in_sizes[1];
    const int B = (int)(((long long)in_sizes[0]) / ((long long)N * CCH));

    // Recover max_win_size (and output layout) from out_size.
    const long long denom = (long long)B * NW * CCH;   // elems per p-slot
    const long long tail  = (long long)N + NW;         // order + counts
    const long long osz   = (long long)out_size;

    int maxw, concat;
    if (osz >= tail && ((osz - tail) % denom) == 0) {
        concat = 1;
        maxw   = (int)((osz - tail) / denom);
    } else {
        concat = 0;
        maxw   = (int)(osz / denom);
    }

    float* out      = (float*)d_out;
    long long winEl = denom * (long long)maxw;
    float* order_f  = out + winEl;
    float* counts_f = order_f + N;

    k_clear<<<1, 256>>>();

    int hgrid = (N + 255) / 256;
    if (hgrid > 160) hgrid = 160;
    k_hist<<<hgrid, 256>>>(wid, N);

    k_scan<<<1, 256>>>(counts_f, concat);

    k_order<<<NW, 256>>>(wid, N, order_f, concat);

    int rows = B * NW * maxw;
    long long totThreads = (long long)rows * 32;
    int tgrid = (int)((totThreads + 255) / 256);
    k_gather<<<tgrid, 256>>>((const float4*)x, (float4*)out, N, maxw, rows);
}

// round 4
// speedup vs baseline: 1.2747x; 1.2747x over previous
#include <cuda_runtime.h>

#define NW   162
#define CCH  128          // channels
#define CV4  (CCH / 4)    // float4 per row
#define MAXN 65536
#define MAXT (MAXN / 32)  // max warp-tiles

// Scratch (allocation-free rule: __device__ globals)
__device__ int g_counts[NW];
__device__ int g_offsets[NW];
__device__ int g_order[MAXN];
__device__ int g_tileHist[MAXT * NW];   // [tile][window], scanned in place

// ---------------------------------------------------------------- zero table
__global__ void k_zero(int n) {
    int i = blockIdx.x * blockDim.x + threadIdx.x;
    if (i < n) g_tileHist[i] = 0;
}

// ------------------------------------------- pass A: per-tile histograms
// One warp handles one 32-element tile. match_any groups equal window ids;
// the group leader writes the group size. Distinct tiles -> no races.
__global__ void k_tilehist(const int* __restrict__ wid, int N) {
    int i = blockIdx.x * blockDim.x + threadIdx.x;
    unsigned active = __ballot_sync(0xffffffffu, i < N);
    if (i >= N) return;
    int w = wid[i];
    unsigned m = __match_any_sync(active, w);
    int lane = threadIdx.x & 31;
    if (lane == (__ffs(m) - 1)) {
        int tile = i >> 5;
        g_tileHist[tile * NW + w] = __popc(m);
    }
}

// -------------------------- pass B1: per-window exclusive scan over tiles
// One warp per window; 1281-entry column scanned with shfl carry loop.
// Also produces the per-window total -> g_counts.
__global__ void k_colscan(int T) {
    int w    = blockIdx.x;
    int lane = threadIdx.x;
    int carry = 0;
    for (int t0 = 0; t0 < T; t0 += 32) {
        int t = t0 + lane;
        int v = (t < T) ? g_tileHist[t * NW + w] : 0;
        int s = v;
#pragma unroll
        for (int d = 1; d < 32; d <<= 1) {
            int u = __shfl_up_sync(0xffffffffu, s, d);
            if (lane >= d) s += u;
        }
        if (t < T) g_tileHist[t * NW + w] = carry + s - v;  // exclusive
        carry += __shfl_sync(0xffffffffu, s, 31);
    }
    if (lane == 0) g_counts[w] = carry;
}

// -------------------------- pass B2: cross-window offsets + counts tail
__global__ void k_offsets(float* __restrict__ counts_f, int write_tail) {
    if (threadIdx.x == 0) {
        int run = 0;
        for (int w = 0; w < NW; ++w) {
            g_offsets[w] = run;
            run += g_counts[w];
        }
    }
    __syncthreads();
    if (write_tail) {
        for (int w = threadIdx.x; w < NW; w += blockDim.x)
            counts_f[w] = (float)g_counts[w];
    }
}

// -------------------------- pass C: stable rank + scatter of order
__global__ void k_rank(const int* __restrict__ wid, int N,
                       float* __restrict__ order_f, int write_tail) {
    int i = blockIdx.x * blockDim.x + threadIdx.x;
    unsigned active = __ballot_sync(0xffffffffu, i < N);
    if (i >= N) return;
    int w = wid[i];
    unsigned m = __match_any_sync(active, w);
    int lane = threadIdx.x & 31;
    int rank = __popc(m & ((1u << lane) - 1u));
    int tile = i >> 5;
    int pos  = g_offsets[w] + g_tileHist[tile * NW + w] + rank;
    g_order[pos] = i;
    if (write_tail) order_f[pos] = (float)i;
}

// -------------------------- gather: one warp per output row (b, w, p)
// x and out are each touched exactly once -> streaming ld/st to keep L2
// free for the small index arrays. Padding rows get explicit zeros.
__global__ void k_gather(const float4* __restrict__ x,
                         float4* __restrict__ out,
                         int N, int maxw, int rows) {
    long long gwarp = ((long long)blockIdx.x * blockDim.x + threadIdx.x) >> 5;
    int lane = threadIdx.x & 31;
    if (gwarp >= rows) return;
    int r = (int)gwarp;

    int nwmax = NW * maxw;
    int b   = r / nwmax;
    int rem = r - b * nwmax;
    int w   = rem / maxw;
    int p   = rem - w * maxw;

    float4 v = make_float4(0.f, 0.f, 0.f, 0.f);
    if (p < g_counts[w]) {
        int idx = g_order[g_offsets[w] + p];
        v = __ldcs(&x[((long long)b * N + idx) * CV4 + lane]);
    }
    __stcs(&out[(long long)r * CV4 + lane], v);
}

extern "C" void kernel_launch(void* const* d_in, const int* in_sizes, int n_in,
                              void* d_out, int out_size) {
    const float* x   = (const float*)d_in[0];
    const int*   wid = (const int*)d_in[1];

    const int N = in_sizes[1];
    const int B = (int)(((long long)in_sizes[0]) / ((long long)N * CCH));
    const int T = (N + 31) / 32;

    // Recover max_win_size (and output layout) from out_size.
    const long long denom = (long long)B * NW * CCH;   // elems per p-slot
    const long long tail  = (long long)N + NW;         // order + counts
    const long long osz   = (long long)out_size;

    int maxw, concat;
    if (osz >= tail && ((osz - tail) % denom) == 0) {
        concat = 1;
        maxw   = (int)((osz - tail) / denom);
    } else {
        concat = 0;
        maxw   = (int)(osz / denom);
    }

    float* out      = (float*)d_out;
    long long winEl = denom * (long long)maxw;
    float* order_f  = out + winEl;
    float* counts_f = order_f + N;

    int histN = T * NW;
    k_zero<<<(histN + 255) / 256, 256>>>(histN);

    k_tilehist<<<(N + 255) / 256, 256>>>(wid, N);

    k_colscan<<<NW, 32>>>(T);

    k_offsets<<<1, 256>>>(counts_f, concat);

    k_rank<<<(N + 255) / 256, 256>>>(wid, N, order_f, concat);

    int rows = B * NW * maxw;
    long long totThreads = (long long)rows * 32;
    int tgrid = (int)((totThreads + 255) / 256);
    k_gather<<<tgrid, 256>>>((const float4*)x, (float4*)out, N, maxw, rows);
}

// round 5
// speedup vs baseline: 1.6915x; 1.3270x over previous
#include <cuda_runtime.h>

#define NW   162
#define CCH  128          // channels
#define CV4  (CCH / 4)    // float4 per row
#define MAXN 65536
#define MAXT (MAXN / 32)  // max warp-tiles

// Scratch (allocation-free rule: __device__ globals)
__device__ int g_counts[NW];
__device__ int g_offsets[NW];
__device__ int g_order[MAXN];
// COLUMN-MAJOR: g_tileHist[w * T + t]  (coalesced column scans)
__device__ int g_tileHist[NW * MAXT];

// ---------------------------------------------------------------- zero table
__global__ void k_zero(int n4) {
    int i = blockIdx.x * blockDim.x + threadIdx.x;
    if (i < n4) ((int4*)g_tileHist)[i] = make_int4(0, 0, 0, 0);
}

// ------------------------------------------- pass A: per-tile histograms
// One warp per 32-element tile; match_any groups equal ids, leader writes
// the group size into the column-major table (scattered 4B writes, ~36K).
__global__ void k_tilehist(const int* __restrict__ wid, int N, int T) {
    int i = blockIdx.x * blockDim.x + threadIdx.x;
    unsigned active = __ballot_sync(0xffffffffu, i < N);
    if (i >= N) return;
    int w = wid[i];
    unsigned m = __match_any_sync(active, w);
    int lane = threadIdx.x & 31;
    if (lane == (__ffs(m) - 1)) {
        int tile = i >> 5;
        g_tileHist[w * T + tile] = __popc(m);
    }
}

// -------------------- pass B1: per-window exclusive scan over tiles
// One 256-thread block per window; its row is CONTIGUOUS (coalesced).
__global__ void k_colscan(int T) {
    const int w    = blockIdx.x;
    int* __restrict__ row = &g_tileHist[w * T];
    __shared__ int wsum[8];
    const int lane = threadIdx.x & 31;
    const int wu   = threadIdx.x >> 5;

    int carry = 0;
    for (int t0 = 0; t0 < T; t0 += 256) {
        int t = t0 + threadIdx.x;
        int v = (t < T) ? row[t] : 0;
        int s = v;
#pragma unroll
        for (int d = 1; d < 32; d <<= 1) {
            int u = __shfl_up_sync(0xffffffffu, s, d);
            if (lane >= d) s += u;
        }
        if (lane == 31) wsum[wu] = s;
        __syncthreads();
        int pre = 0, tot = 0;
#pragma unroll
        for (int j = 0; j < 8; ++j) {
            int ws = wsum[j];
            tot += ws;
            if (j < wu) pre += ws;
        }
        if (t < T) row[t] = carry + pre + s - v;   // exclusive
        carry += tot;
        __syncthreads();   // wsum reuse next round
    }
    if (threadIdx.x == 0) g_counts[w] = carry;
}

// ---------------- pass B2: cross-window offsets (single-warp shfl scan)
__global__ void k_offsets(float* __restrict__ counts_f, int write_tail) {
    const int lane = threadIdx.x & 31;
    if (threadIdx.x < 32) {
        int carry = 0;
#pragma unroll
        for (int c0 = 0; c0 < NW; c0 += 32) {
            int w = c0 + lane;
            int v = (w < NW) ? g_counts[w] : 0;
            int s = v;
#pragma unroll
            for (int d = 1; d < 32; d <<= 1) {
                int u = __shfl_up_sync(0xffffffffu, s, d);
                if (lane >= d) s += u;
            }
            if (w < NW) g_offsets[w] = carry + s - v;   // exclusive
            carry += __shfl_sync(0xffffffffu, s, 31);
        }
    }
    __syncthreads();
    if (write_tail) {
        for (int w = threadIdx.x; w < NW; w += blockDim.x)
            counts_f[w] = (float)g_counts[w];
    }
}

// -------------------------- pass C: stable rank + scatter of order
__global__ void k_rank(const int* __restrict__ wid, int N, int T,
                       float* __restrict__ order_f, int write_tail) {
    int i = blockIdx.x * blockDim.x + threadIdx.x;
    unsigned active = __ballot_sync(0xffffffffu, i < N);
    if (i >= N) return;
    int w = wid[i];
    unsigned m = __match_any_sync(active, w);
    int lane = threadIdx.x & 31;
    int rank = __popc(m & ((1u << lane) - 1u));
    int tile = i >> 5;
    int pos  = g_offsets[w] + g_tileHist[w * T + tile] + rank;
    g_order[pos] = i;
    if (write_tail) order_f[pos] = (float)i;
}

// -------------------------- gather: 4 rows per warp (MLP=4)
// Front-batch 4 independent float4 loads, then 4 streaming stores.
__global__ void k_gather(const float4* __restrict__ x,
                         float4* __restrict__ out,
                         int N, int maxw, int rows) {
    int warp = (int)(((long long)blockIdx.x * blockDim.x + threadIdx.x) >> 5);
    int lane = threadIdx.x & 31;
    int r0 = warp * 4;
    if (r0 >= rows) return;

    const int nwmax = NW * maxw;
    long long src[4];
    bool valid[4];

#pragma unroll
    for (int j = 0; j < 4; ++j) {
        int r = r0 + j;
        valid[j] = false;
        src[j] = 0;
        if (r < rows) {
            int b   = r / nwmax;
            int rem = r - b * nwmax;
            int w   = rem / maxw;
            int p   = rem - w * maxw;
            if (p < g_counts[w]) {
                int idx = g_order[g_offsets[w] + p];
                src[j]  = ((long long)b * N + idx) * CV4 + lane;
                valid[j] = true;
            }
        }
    }

    float4 v[4];
#pragma unroll
    for (int j = 0; j < 4; ++j)
        v[j] = valid[j] ? __ldcs(&x[src[j]]) : make_float4(0.f, 0.f, 0.f, 0.f);

#pragma unroll
    for (int j = 0; j < 4; ++j)
        if (r0 + j < rows)
            __stcs(&out[(long long)(r0 + j) * CV4 + lane], v[j]);
}

extern "C" void kernel_launch(void* const* d_in, const int* in_sizes, int n_in,
                              void* d_out, int out_size) {
    const float* x   = (const float*)d_in[0];
    const int*   wid = (const int*)d_in[1];

    const int N = in_sizes[1];
    const int B = (int)(((long long)in_sizes[0]) / ((long long)N * CCH));
    const int T = (N + 31) / 32;

    // Recover max_win_size (and output layout) from out_size.
    const long long denom = (long long)B * NW * CCH;   // elems per p-slot
    const long long tail  = (long long)N + NW;         // order + counts
    const long long osz   = (long long)out_size;

    int maxw, concat;
    if (osz >= tail && ((osz - tail) % denom) == 0) {
        concat = 1;
        maxw   = (int)((osz - tail) / denom);
    } else {
        concat = 0;
        maxw   = (int)(osz / denom);
    }

    float* out      = (float*)d_out;
    long long winEl = denom * (long long)maxw;
    float* order_f  = out + winEl;
    float* counts_f = order_f + N;

    int histInts = NW * T;
    int histN4   = (histInts + 3) / 4;          // table is padded (NW*MAXT)
    k_zero<<<(histN4 + 255) / 256, 256>>>(histN4);

    k_tilehist<<<(N + 255) / 256, 256>>>(wid, N, T);

    k_colscan<<<NW, 256>>>(T);

    k_offsets<<<1, 256>>>(counts_f, concat);

    k_rank<<<(N + 255) / 256, 256>>>(wid, N, T, order_f, concat);

    int rows  = B * NW * maxw;
    int warps = (rows + 3) / 4;
    long long totThreads = (long long)warps * 32;
    int tgrid = (int)((totThreads + 255) / 256);
    k_gather<<<tgrid, 256>>>((const float4*)x, (float4*)out, N, maxw, rows);
}